// round 5
// baseline (speedup 1.0000x reference)
#include <cuda_runtime.h>
#include <cstdint>

#define Hh 512
#define Ww 512
#define Cc 32
#define Bb 4
#define Ss (Hh*Ww)

#define TS 32                  // output tile (32x32)
#define HP 5                   // halo pad each side
#define HW (TS + 2*HP)         // 42: staged window width/height
#define TILE_ELEMS (HW*HW)     // 1764 floats per channel
// dynamic smem: 32ch * 1764 * 4B = 225792 + weights 288*8 = 2304 -> 228096 B
#define SMEM_BYTES (Cc*TILE_ELEMS*4 + 288*8)

typedef unsigned long long ull;

__device__ __forceinline__ ull pack2(float a, float b) {
    ull r; asm("mov.b64 %0, {%1, %2};" : "=l"(r) : "f"(a), "f"(b)); return r;
}
__device__ __forceinline__ void unpack2(ull v, float& a, float& b) {
    asm("mov.b64 {%0, %1}, %2;" : "=f"(a), "=f"(b) : "l"(v));
}
__device__ __forceinline__ ull fma2(ull a, ull b, ull c) {
    ull d; asm("fma.rn.f32x2 %0, %1, %2, %3;" : "=l"(d) : "l"(a), "l"(b), "l"(c)); return d;
}

// ---------------------------------------------------------------------------
// Fused deformable conv: per 32x32 tile, stage ALL 32 channels of a 42x42
// halo window once (225.8KB smem). The offset conv (only channels 0,1 of the
// 18 are consumed by the reference) and the bilinear sampling both read from
// this staged window: x is read from DRAM exactly once (plus 1.56x halo),
// the offset scratch buffer and second kernel disappear.
//
// Sampling fast path: raw (unclamped) corner coords indexed into the staged
// window. Staged zeros outside the image reproduce the reference's
// zero-validity-weight semantics exactly. Corners outside the +-5 halo
// (P ~ 1e-7 per pixel) take a global-memory fallback path.
// ---------------------------------------------------------------------------
__global__ __launch_bounds__(256) void fused_deform_kernel(
    const float* __restrict__ x,
    const float* __restrict__ w_off,
    const float* __restrict__ b_off,
    float* __restrict__ out)
{
    extern __shared__ float smem[];
    float*  s_x = smem;                                  // [32][1764]
    float2* s_w = (float2*)(smem + Cc * TILE_ELEMS);     // [288] packed (w0,w1)

    const int tid = threadIdx.x;
    const int wrp = tid >> 5, lan = tid & 31;
    const int tx = tid & 15;       // pixel cols 2tx, 2tx+1
    const int ty = tid >> 4;       // pixel rows 2ty, 2ty+1
    const int bx = blockIdx.x, by = blockIdx.y, bz = blockIdx.z;

    const int gx0 = bx * TS, gy0 = by * TS;
    const int ox = gx0 - HP, oy = gy0 - HP;   // staged-window origin

    // ---- stage weights (packed) ----
    for (int i = tid; i < Cc * 9; i += 256)
        s_w[i] = make_float2(__ldg(w_off + i), __ldg(w_off + 288 + i));

    // ---- stage 32 channels of the 42x42 window (zero-filled outside) ----
    const float* xb = x + (size_t)bz * Cc * Ss;
    for (int c = 0; c < Cc; c++) {
        const float* xc = xb + (size_t)c * Ss;
        float* buf = s_x + c * TILE_ELEMS;
        for (int r = wrp; r < HW; r += 8) {
            int gy = oy + r;
            bool rowok = ((unsigned)gy < (unsigned)Hh);
            const float* rowp = xc + gy * Ww;
#pragma unroll
            for (int j = lan; j < HW; j += 32) {
                int gx = ox + j;
                float v = 0.0f;
                if (rowok && (unsigned)gx < (unsigned)Ww) v = __ldg(rowp + gx);
                buf[r * HW + j] = v;
            }
        }
    }
    __syncthreads();

    // ---- offset conv: 2x2 pixels per thread, packed (off_x, off_y) f32x2 ----
    const float b0v = __ldg(b_off + 0);
    const float b1v = __ldg(b_off + 1);
    ull acc[4];
    const ull biasp = pack2(b0v, b1v);
#pragma unroll
    for (int i = 0; i < 4; i++) acc[i] = biasp;

    for (int c = 0; c < Cc; c++) {
        const float* curp = s_x + c * TILE_ELEMS;

        ull wk[9];
#pragma unroll
        for (int k = 0; k < 9; k++) {
            float2 t = s_w[c * 9 + k];
            wk[k] = pack2(t.x, t.y);
        }

        // 4x4 window at staged (2ty+4, 2tx+4): 4 rows x 2 aligned LDS.64
        ull pv[4][4];
#pragma unroll
        for (int r = 0; r < 4; r++) {
            const float2* rp = reinterpret_cast<const float2*>(
                curp + (2 * ty + 4 + r) * HW + 2 * tx + 4);
            float2 a = rp[0];
            float2 bq = rp[1];
            pv[r][0] = pack2(a.x, a.x);
            pv[r][1] = pack2(a.y, a.y);
            pv[r][2] = pack2(bq.x, bq.x);
            pv[r][3] = pack2(bq.y, bq.y);
        }

#pragma unroll
        for (int pr = 0; pr < 2; pr++) {
#pragma unroll
            for (int pc = 0; pc < 2; pc++) {
                ull a = acc[pr * 2 + pc];
#pragma unroll
                for (int ky = 0; ky < 3; ky++) {
#pragma unroll
                    for (int kx = 0; kx < 3; kx++) {
                        a = fma2(pv[pr + ky][pc + kx], wk[ky * 3 + kx], a);
                    }
                }
                acc[pr * 2 + pc] = a;
            }
        }
    }

    // ---- per-pixel sampling setup ----
    int   s00[4];
    float w00[4], w01[4], w10[4], w11[4];
    bool  fastp[4];
    float ixs[4], iys[4];

#pragma unroll
    for (int p = 0; p < 4; p++) {
        int pr = p >> 1, pc = p & 1;
        int px = gx0 + 2 * tx + pc;
        int py = gy0 + 2 * ty + pr;
        float offx, offy;
        unpack2(acc[pr * 2 + pc], offx, offy);
        float ix = (float)px + offx;
        float iy = (float)py + offy;
        ixs[p] = ix; iys[p] = iy;

        float x0f = floorf(ix);
        float y0f = floorf(iy);
        float sxf = x0f - (float)ox;    // integral by construction
        float syf = y0f - (float)oy;
        bool fast = (sxf >= 0.0f) & (sxf <= (float)(HW - 2)) &
                    (syf >= 0.0f) & (syf <= (float)(HW - 2));
        fastp[p] = fast;

        float wx1 = ix - x0f, wx0 = 1.0f - wx1;
        float wy1 = iy - y0f, wy0 = 1.0f - wy1;
        if (fast) {
            s00[p] = (int)syf * HW + (int)sxf;
            w00[p] = wy0 * wx0; w01[p] = wy0 * wx1;
            w10[p] = wy1 * wx0; w11[p] = wy1 * wx1;
        } else {
            s00[p] = 0;
            w00[p] = w01[p] = w10[p] = w11[p] = 0.0f;  // overwritten by fallback
        }
    }

    // ---- main sampling loop over channels (smem gather, coalesced stores) ----
    const size_t obase = (size_t)bz * Cc * Ss
                       + (size_t)(gy0 + 2 * ty) * Ww + (gx0 + 2 * tx);
#pragma unroll 2
    for (int c = 0; c < Cc; c++) {
        const float* base = s_x + c * TILE_ELEMS;
        float v[4];
#pragma unroll
        for (int p = 0; p < 4; p++) {
            int s = s00[p];
            v[p] = w00[p] * base[s]
                 + w01[p] * base[s + 1]
                 + w10[p] * base[s + HW]
                 + w11[p] * base[s + HW + 1];
        }
        float* op = out + obase + (size_t)c * Ss;
        __stcs(reinterpret_cast<float2*>(op),       make_float2(v[0], v[1]));
        __stcs(reinterpret_cast<float2*>(op + Ww),  make_float2(v[2], v[3]));
    }

    // ---- rare fallback: corners outside staged window -> global path ----
#pragma unroll
    for (int p = 0; p < 4; p++) {
        if (!fastp[p]) {
            int pr = p >> 1, pc = p & 1;
            int px = gx0 + 2 * tx + pc;
            int py = gy0 + 2 * ty + pr;
            float ix = ixs[p], iy = iys[p];
            float x0f = floorf(ix), y0f = floorf(iy);
            float wx1 = ix - x0f, wx0 = 1.0f - wx1;
            float wy1 = iy - y0f, wy0 = 1.0f - wy1;
            float fx0 = (x0f >= 0.0f && x0f <= 511.0f) ? 1.0f : 0.0f;
            float fx1 = (x0f >= -1.0f && x0f <= 510.0f) ? 1.0f : 0.0f;
            float fy0 = (y0f >= 0.0f && y0f <= 511.0f) ? 1.0f : 0.0f;
            float fy1 = (y0f >= -1.0f && y0f <= 510.0f) ? 1.0f : 0.0f;
            int ix0r = (int)x0f, iy0r = (int)y0f;
            int xi0 = max(0, min(511, ix0r));
            int xi1 = max(0, min(511, ix0r + 1));
            int yi0 = max(0, min(511, iy0r));
            int yi1 = max(0, min(511, iy0r + 1));
            float g00 = wy0 * wx0 * (fy0 * fx0);
            float g01 = wy0 * wx1 * (fy0 * fx1);
            float g10 = wy1 * wx0 * (fy1 * fx0);
            float g11 = wy1 * wx1 * (fy1 * fx1);
            int i00 = yi0 * Ww + xi0, i01 = yi0 * Ww + xi1;
            int i10 = yi1 * Ww + xi0, i11 = yi1 * Ww + xi1;
            for (int c = 0; c < Cc; c++) {
                const float* pch = xb + (size_t)c * Ss;
                float vv = g00 * __ldg(pch + i00) + g01 * __ldg(pch + i01)
                         + g10 * __ldg(pch + i10) + g11 * __ldg(pch + i11);
                out[(size_t)bz * Cc * Ss + (size_t)c * Ss + (size_t)py * Ww + px] = vv;
            }
        }
    }
}

extern "C" void kernel_launch(void* const* d_in, const int* in_sizes, int n_in,
                              void* d_out, int out_size)
{
    const float* x     = (const float*)d_in[0];  // (4, 32, 512, 512)
    const float* w_off = (const float*)d_in[1];  // (18, 32, 3, 3)
    const float* b_off = (const float*)d_in[2];  // (18,)
    float* out = (float*)d_out;                  // (4, 32, 512, 512)

    (void)in_sizes; (void)n_in; (void)out_size;

    cudaFuncSetAttribute(fused_deform_kernel,
                         cudaFuncAttributeMaxDynamicSharedMemorySize, SMEM_BYTES);

    dim3 grid(Ww / TS, Hh / TS, Bb);
    fused_deform_kernel<<<grid, 256, SMEM_BYTES>>>(x, w_off, b_off, out);
}

// round 6
// speedup vs baseline: 5.2897x; 5.2897x over previous
#include <cuda_runtime.h>
#include <cstdint>

#define Hh 512
#define Ww 512
#define Cc 32
#define Bb 4
#define Ss (Hh*Ww)

// Scratch: per-pixel (off_x, off_y), 4*512*512*8B = 8 MB
__device__ float2 g_off_buf[Bb * Ss];

typedef unsigned long long ull;

__device__ __forceinline__ ull pack2(float a, float b) {
    ull r; asm("mov.b64 %0, {%1, %2};" : "=l"(r) : "f"(a), "f"(b)); return r;
}
__device__ __forceinline__ void unpack2(ull v, float& a, float& b) {
    asm("mov.b64 {%0, %1}, %2;" : "=f"(a), "=f"(b) : "l"(v));
}
__device__ __forceinline__ ull fma2(ull a, ull b, ull c) {
    ull d; asm("fma.rn.f32x2 %0, %1, %2, %3;" : "=l"(d) : "l"(a), "l"(b), "l"(c)); return d;
}

// ---------------------------------------------------------------------------
// Kernel 1: offset conv (only channels 0,1 of the 18 are consumed downstream).
// 32x32 tile, 256 threads (thread = 2x2 px), channels staged in groups of 8.
//
// R6 fix: the 41.5KB tile buffer moves from STATIC smem (48KB limit -> 1
// block/SM -> 8 warps, latency-exposed, ~92us) to DYNAMIC smem (228KB
// carveout -> 5 blocks/SM -> 40 warps/SM). Same code path otherwise.
// ---------------------------------------------------------------------------
#define CG 8              // channels per staging group
#define TPITCH 36         // padded smem row pitch (floats)
#define CONV_SMEM (CG * 34 * TPITCH * 4 + Cc * 9 * 8)   // 39168 + 2304 = 41472B

__global__ __launch_bounds__(256) void conv_off_kernel(
    const float* __restrict__ x,
    const float* __restrict__ w_off,
    const float* __restrict__ b_off)
{
    extern __shared__ float dsm[];
    float*  s_tile = dsm;                          // [CG][34*TPITCH]
    float2* s_w    = (float2*)(dsm + CG * 34 * TPITCH);  // [288]

    const int tid = threadIdx.x;
    const int tx = tid & 15;    // 2*tx .. 2*tx+1 cols
    const int ty = tid >> 4;    // 2*ty .. 2*ty+1 rows
    const int bx = blockIdx.x, by = blockIdx.y, bz = blockIdx.z;

    for (int i = tid; i < Cc * 9; i += 256)
        s_w[i] = make_float2(__ldg(w_off + i), __ldg(w_off + 288 + i));

    const int gx0 = bx * 32 - 1;
    const int gy0 = by * 32 - 1;
    const float* xb = x + (size_t)bz * Cc * Ss;

    const float b0v = __ldg(b_off + 0);
    const float b1v = __ldg(b_off + 1);

    ull acc[4];
    const ull biasp = pack2(b0v, b1v);
#pragma unroll
    for (int i = 0; i < 4; i++) acc[i] = biasp;

    for (int g = 0; g < Cc / CG; g++) {
        // ---- stage 8 channels (high-MLP, bandwidth-bound) ----
#pragma unroll
        for (int c8 = 0; c8 < CG; c8++) {
            const float* xc = xb + (size_t)(g * CG + c8) * Ss;
            float* buf = s_tile + c8 * (34 * TPITCH);
#pragma unroll
            for (int i = tid; i < 34 * 34; i += 256) {
                int r = i / 34;
                int q = i - r * 34;
                int gy = gy0 + r;
                int gx = gx0 + q;
                float v = 0.0f;
                if ((unsigned)gy < (unsigned)Hh && (unsigned)gx < (unsigned)Ww)
                    v = __ldg(xc + gy * Ww + gx);
                buf[r * TPITCH + q] = v;
            }
        }
        __syncthreads();

        // ---- compute 8 channels from smem ----
#pragma unroll
        for (int c8 = 0; c8 < CG; c8++) {
            const float* curp = s_tile + c8 * (34 * TPITCH);

            ull wk[9];
#pragma unroll
            for (int k = 0; k < 9; k++) {
                float2 t = s_w[(g * CG + c8) * 9 + k];
                wk[k] = pack2(t.x, t.y);
            }

            // 4x4 input window at (2ty, 2tx): 4 rows x 2 aligned LDS.64
            ull pv[4][4];
#pragma unroll
            for (int r = 0; r < 4; r++) {
                const float2* rp = reinterpret_cast<const float2*>(
                    curp + (2 * ty + r) * TPITCH + 2 * tx);
                float2 a = rp[0];
                float2 bq = rp[1];
                pv[r][0] = pack2(a.x, a.x);
                pv[r][1] = pack2(a.y, a.y);
                pv[r][2] = pack2(bq.x, bq.x);
                pv[r][3] = pack2(bq.y, bq.y);
            }

#pragma unroll
            for (int pr = 0; pr < 2; pr++) {
#pragma unroll
                for (int pc = 0; pc < 2; pc++) {
                    ull a = acc[pr * 2 + pc];
#pragma unroll
                    for (int ky = 0; ky < 3; ky++) {
#pragma unroll
                        for (int kx = 0; kx < 3; kx++) {
                            a = fma2(pv[pr + ky][pc + kx], wk[ky * 3 + kx], a);
                        }
                    }
                    acc[pr * 2 + pc] = a;
                }
            }
        }
        __syncthreads();
    }

    // write offsets (single-use scratch: streaming stores, keep L2 for x)
#pragma unroll
    for (int pr = 0; pr < 2; pr++) {
#pragma unroll
        for (int pc = 0; pc < 2; pc++) {
            int y = by * 32 + 2 * ty + pr;
            int xcol = bx * 32 + 2 * tx + pc;
            float ox, oy;
            unpack2(acc[pr * 2 + pc], ox, oy);
            __stcs(&g_off_buf[bz * Ss + y * Ww + xcol], make_float2(ox, oy));
        }
    }
}

// ---------------------------------------------------------------------------
// Kernel 2: bilinear sampling with zero padding. One thread per pixel, 32
// channels looped with corner indices/weights hoisted. Corner clamping and
// validity handled independently from the raw integer coords (jnp semantics).
// ---------------------------------------------------------------------------
__global__ __launch_bounds__(256) void sample_kernel(
    const float* __restrict__ x,
    float* __restrict__ out)
{
    const int px = blockIdx.x * 64 + threadIdx.x;
    const int py = blockIdx.y * 4 + threadIdx.y;
    const int b  = blockIdx.z;

    float2 off = __ldcs(&g_off_buf[b * Ss + py * Ww + px]);
    float ix = (float)px + off.x;
    float iy = (float)py + off.y;

    float x0f = floorf(ix);
    float y0f = floorf(iy);
    float wx1 = ix - x0f, wx0 = 1.0f - wx1;
    float wy1 = iy - y0f, wy0 = 1.0f - wy1;

    float fx0 = (x0f >= 0.0f && x0f <= 511.0f) ? 1.0f : 0.0f;
    float fx1 = (x0f >= -1.0f && x0f <= 510.0f) ? 1.0f : 0.0f;
    float fy0 = (y0f >= 0.0f && y0f <= 511.0f) ? 1.0f : 0.0f;
    float fy1 = (y0f >= -1.0f && y0f <= 510.0f) ? 1.0f : 0.0f;

    int ix0r = (int)x0f;
    int iy0r = (int)y0f;
    int xi0 = max(0, min(511, ix0r));
    int xi1 = max(0, min(511, ix0r + 1));
    int yi0 = max(0, min(511, iy0r));
    int yi1 = max(0, min(511, iy0r + 1));

    float w00 = wy0 * wx0 * (fy0 * fx0);
    float w01 = wy0 * wx1 * (fy0 * fx1);
    float w10 = wy1 * wx0 * (fy1 * fx0);
    float w11 = wy1 * wx1 * (fy1 * fx1);

    const int i00 = yi0 * Ww + xi0;
    const int i01 = yi0 * Ww + xi1;
    const int i10 = yi1 * Ww + xi0;
    const int i11 = yi1 * Ww + xi1;

    const float* xb = x + (size_t)b * Cc * Ss;
    size_t o = (size_t)b * Cc * Ss + (size_t)py * Ww + px;

#pragma unroll 4
    for (int c = 0; c < Cc; c++) {
        const float* p = xb + (size_t)c * Ss;
        float v = w00 * __ldg(p + i00)
                + w01 * __ldg(p + i01)
                + w10 * __ldg(p + i10)
                + w11 * __ldg(p + i11);
        __stcs(out + o + (size_t)c * Ss, v);
    }
}

extern "C" void kernel_launch(void* const* d_in, const int* in_sizes, int n_in,
                              void* d_out, int out_size)
{
    const float* x     = (const float*)d_in[0];  // (4, 32, 512, 512)
    const float* w_off = (const float*)d_in[1];  // (18, 32, 3, 3)
    const float* b_off = (const float*)d_in[2];  // (18,)
    float* out = (float*)d_out;                  // (4, 32, 512, 512)

    (void)in_sizes; (void)n_in; (void)out_size;

    cudaFuncSetAttribute(conv_off_kernel,
                         cudaFuncAttributeMaxDynamicSharedMemorySize, CONV_SMEM);

    dim3 g1(Ww / 32, Hh / 32, Bb);
    conv_off_kernel<<<g1, 256, CONV_SMEM>>>(x, w_off, b_off);

    dim3 g2(Ww / 64, Hh / 4, Bb);
    dim3 t2(64, 4);
    sample_kernel<<<g2, t2>>>(x, out);
}